// round 1
// baseline (speedup 1.0000x reference)
#include <cuda_runtime.h>
#include <cstdint>

// Problem dims (fixed by the dataset)
#define B_N   2048          // batch (= hash_size = D+1)
#define D_IN  2047          // state dim
#define NIN   2048          // inner GEMM dim = D+1
#define K_N   4096          // input_length (number of hyperplanes)
#define TABLE_MASK ((1 << 22) - 1)

// Scratch (device globals: allocation-free, graph-capturable)
__device__ float g_X[B_N * NIN];     // packed [states | actions], row-major [2048][2048]
__device__ int   g_acc[B_N];         // per-batch hash accumulator (int32, wraps like the reference)

// ---------------------------------------------------------------------------
// Kernel 1: pack X and zero accumulators
// ---------------------------------------------------------------------------
__global__ __launch_bounds__(256) void pack_kernel(const float* __restrict__ states,
                                                   const float* __restrict__ actions)
{
    int t = blockIdx.x * blockDim.x + threadIdx.x;
    if (t < B_N) g_acc[t] = 0;
    if (t < B_N * NIN) {
        int j = t >> 11;           // t / 2048
        int d = t & (NIN - 1);     // t % 2048
        g_X[t] = (d < D_IN) ? states[j * D_IN + d] : actions[j];
    }
}

// ---------------------------------------------------------------------------
// Kernel 2: fused SGEMM + sign + hash partial-sum
//   C[j,k] = sum_d X[j,d] * A[k,d]        (both operands d-major / K-major)
//   bit    = (C[j,k] + b[j]) > 0
//   acc[j]+= bit ? hc[k] : 0              (int32 wraparound ok; mod 2^22 later)
//
// 128x128 block tile, kt=8, 256 threads, 8x8 register micro-tile per thread.
// ---------------------------------------------------------------------------
#define TILE 128
#define KT   8

__global__ __launch_bounds__(256, 2) void gemm_sign_hash(
    const float* __restrict__ A,
    const float* __restrict__ b,
    const int*   __restrict__ hc)
{
    __shared__ float Xs[KT][TILE + 4];
    __shared__ float As[KT][TILE + 4];

    const int tid = threadIdx.x;
    const int tx  = tid & 15;        // 0..15  -> k sub-tiles
    const int ty  = tid >> 4;        // 0..15  -> j sub-tiles
    const int jBase = blockIdx.y * TILE;
    const int kBase = blockIdx.x * TILE;

    // Per-tile global loads: each thread loads one float4 of X and one of A.
    const int lrow = tid >> 1;           // 0..127
    const int lcol = (tid & 1) * 4;      // 0 or 4
    const float* Xp = g_X + (size_t)(jBase + lrow) * NIN + lcol;
    const float* Ap = A   + (size_t)(kBase + lrow) * NIN + lcol;

    float c[8][8];
    #pragma unroll
    for (int i = 0; i < 8; ++i)
        #pragma unroll
        for (int ii = 0; ii < 8; ++ii) c[i][ii] = 0.f;

    for (int d0 = 0; d0 < NIN; d0 += KT) {
        float4 xv = *(const float4*)(Xp + d0);
        float4 av = *(const float4*)(Ap + d0);
        __syncthreads();                       // previous iter's smem reads done
        Xs[lcol + 0][lrow] = xv.x; Xs[lcol + 1][lrow] = xv.y;
        Xs[lcol + 2][lrow] = xv.z; Xs[lcol + 3][lrow] = xv.w;
        As[lcol + 0][lrow] = av.x; As[lcol + 1][lrow] = av.y;
        As[lcol + 2][lrow] = av.z; As[lcol + 3][lrow] = av.w;
        __syncthreads();

        #pragma unroll
        for (int d = 0; d < KT; ++d) {
            float xr[8], ar[8];
            #pragma unroll
            for (int i = 0; i < 8; ++i) xr[i] = Xs[d][ty * 8 + i];
            #pragma unroll
            for (int i = 0; i < 8; ++i) ar[i] = As[d][tx * 8 + i];
            #pragma unroll
            for (int i = 0; i < 8; ++i)
                #pragma unroll
                for (int ii = 0; ii < 8; ++ii)
                    c[i][ii] = fmaf(xr[i], ar[ii], c[i][ii]);
        }
    }

    // Epilogue: sign -> select hash coeff -> reduce across the 16 k-threads of a row
    int hcreg[8];
    #pragma unroll
    for (int ii = 0; ii < 8; ++ii) hcreg[ii] = hc[kBase + tx * 8 + ii];

    #pragma unroll
    for (int i = 0; i < 8; ++i) {
        const int j = jBase + ty * 8 + i;
        const float bias = __ldg(&b[j]);
        int local = 0;
        #pragma unroll
        for (int ii = 0; ii < 8; ++ii)
            local += (c[i][ii] + bias > 0.f) ? hcreg[ii] : 0;
        // reduce over the 16 lanes (tx) sharing this row; tx == lane%16 by construction
        #pragma unroll
        for (int off = 8; off > 0; off >>= 1)
            local += __shfl_down_sync(0xFFFFFFFFu, local, off, 16);
        if (tx == 0)
            atomicAdd(&g_acc[j], local);
    }
}

// ---------------------------------------------------------------------------
// Kernel 3: mod, gather, map
// ---------------------------------------------------------------------------
__global__ __launch_bounds__(256) void finalize_kernel(const int* __restrict__ table,
                                                       float* __restrict__ out)
{
    int j = blockIdx.x * blockDim.x + threadIdx.x;
    if (j < B_N) {
        // TABLE = 2^22: two's-complement bit-mask == jnp.mod (non-negative result)
        int idx = g_acc[j] & TABLE_MASK;
        float cp1 = (float)table[idx] + 1.0f;
        out[j] = 1.0f / (cp1 * cp1);
    }
}

// ---------------------------------------------------------------------------
// Launch. Inputs (metadata order): states, actions, A, b, count_table, hash_coeffs
// ---------------------------------------------------------------------------
extern "C" void kernel_launch(void* const* d_in, const int* in_sizes, int n_in,
                              void* d_out, int out_size)
{
    const float* states  = (const float*)d_in[0];
    const float* actions = (const float*)d_in[1];
    const float* A       = (const float*)d_in[2];
    const float* b       = (const float*)d_in[3];
    const int*   table   = (const int*)  d_in[4];
    const int*   hc      = (const int*)  d_in[5];
    float* out = (float*)d_out;

    pack_kernel<<<(B_N * NIN + 255) / 256, 256>>>(states, actions);

    dim3 grid(K_N / TILE, B_N / TILE);   // (32, 16)
    gemm_sign_hash<<<grid, 256>>>(A, b, hc);

    finalize_kernel<<<(B_N + 255) / 256, 256>>>(table, out);
}

// round 5
// speedup vs baseline: 1.7591x; 1.7591x over previous
#include <cuda_runtime.h>
#include <cuda_bf16.h>
#include <cstdint>

// ---------------------------------------------------------------- dims
#define B_N   2048
#define D_IN  2047
#define NIN   2048
#define K_N   4096
#define TABLE_MASK ((1 << 22) - 1)

#define BM 128
#define BN 128
#define BK 32
#define NCHUNK (NIN / BK)          // 64
#define XPLANE (B_N * NIN)         // 4194304
#define APLANE (K_N * NIN)         // 8388608

#define ROWB  80                   // padded smem row: 32 bf16 = 64B data + 16B pad
#define TILEB (128 * ROWB)         // 10240 B per tile
#define STAGEB (4 * TILEB)         // x0,x1,a0,a1 tiles = 40960 B
#define DYNSMEM (2 * STAGEB)       // double buffer = 81920 B

#define TH   0.05f
#define FCAP 131072

// ---------------------------------------------------------------- scratch
__device__ __align__(16) float          g_Xf[XPLANE];        // fp32 packed X (fixup)
__device__ __align__(16) __nv_bfloat16  g_Xs[2u * XPLANE];   // bf16 split planes of X
__device__ __align__(16) __nv_bfloat16  g_As[2u * APLANE];   // bf16 split planes of A
__device__ int g_acc[B_N];
__device__ int g_nflag;
__device__ int g_flags[FCAP];

// ---------------------------------------------------------------- helpers
__device__ __forceinline__ uint32_t smem_u32(const void* p) {
    uint32_t a;
    asm("{ .reg .u64 t; cvta.to.shared.u64 t, %1; cvt.u32.u64 %0, t; }" : "=r"(a) : "l"(p));
    return a;
}
__device__ __forceinline__ void cp_async16(uint32_t dst, const void* src) {
    asm volatile("cp.async.cg.shared.global [%0], [%1], 16;" :: "r"(dst), "l"(src) : "memory");
}
__device__ __forceinline__ void ldm_x4(uint32_t* r, uint32_t addr) {
    asm volatile("ldmatrix.sync.aligned.m8n8.x4.shared.b16 {%0,%1,%2,%3}, [%4];"
                 : "=r"(r[0]), "=r"(r[1]), "=r"(r[2]), "=r"(r[3]) : "r"(addr));
}
__device__ __forceinline__ void mma16816(float* d, const uint32_t* a, uint32_t b0, uint32_t b1) {
    asm volatile("mma.sync.aligned.m16n8k16.row.col.f32.bf16.bf16.f32 "
                 "{%0,%1,%2,%3},{%4,%5,%6,%7},{%8,%9},{%0,%1,%2,%3};"
                 : "+f"(d[0]), "+f"(d[1]), "+f"(d[2]), "+f"(d[3])
                 : "r"(a[0]), "r"(a[1]), "r"(a[2]), "r"(a[3]), "r"(b0), "r"(b1));
}

// ---------------------------------------------------------------- kernel 1: pack + 2-way bf16 split
__global__ __launch_bounds__(256) void split_kernel(const float* __restrict__ states,
                                                    const float* __restrict__ actions,
                                                    const float* __restrict__ A)
{
    unsigned t = blockIdx.x * 256u + threadIdx.x;
    if (t < B_N) g_acc[t] = 0;
    if (t == 0) g_nflag = 0;

    if (t < XPLANE) {
        unsigned j = t >> 11, d = t & (NIN - 1);
        float v = (d < D_IN) ? states[j * D_IN + d] : actions[j];
        g_Xf[t] = v;
        __nv_bfloat16 h0 = __float2bfloat16_rn(v);
        float r1 = v - __bfloat162float(h0);
        g_Xs[t] = h0;
        g_Xs[t + XPLANE] = __float2bfloat16_rn(r1);
    } else {
        unsigned e = t - XPLANE;
        if (e < APLANE) {
            float v = A[e];
            __nv_bfloat16 h0 = __float2bfloat16_rn(v);
            float r1 = v - __bfloat162float(h0);
            g_As[e] = h0;
            g_As[e + APLANE] = __float2bfloat16_rn(r1);
        }
    }
}

// ---------------------------------------------------------------- kernel 2: HMMA GEMM + sign + hash
// C[j,k] = x0.a0 + x0.a1 + x1.a0  (fp32 accum). sign(C + b[j]) selects hc[k].
// Elements with |C+b| < TH flagged for exact fp32 fixup.
__global__ __launch_bounds__(256, 2) void gemm_tc(const float* __restrict__ b,
                                                  const int*   __restrict__ hc)
{
    extern __shared__ __align__(128) unsigned char dynsmem[];
    const uint32_t sbase = smem_u32(dynsmem);

    const int tid  = threadIdx.x;
    const int wid  = tid >> 5;
    const int lane = tid & 31;
    const int wm   = wid & 1;          // 2 warps over M
    const int wn   = wid >> 1;         // 4 warps over N
    const int jBase = blockIdx.y * BM;
    const int kBase = blockIdx.x * BN;

    // ldmatrix per-lane addressing (m8n8.x4, no trans)
    const int laneRow  = (lane & 7) + ((lane >> 3) & 1) * 8;
    const int laneColB = ((lane >> 4) * 8) * 2;

    float c[4][4][4];
    #pragma unroll
    for (int mi = 0; mi < 4; ++mi)
        #pragma unroll
        for (int ni = 0; ni < 4; ++ni)
            #pragma unroll
            for (int e = 0; e < 4; ++e) c[mi][ni][e] = 0.f;

    // producer: load chunk ch (d-range [ch*32, ch*32+32)) into stage st:
    // 4 tiles: X plane0, X plane1, A plane0, A plane1, each 128 rows x 64B (pad to 80B)
    auto issue_loads = [&](int ch, int st) {
        const int d0 = ch << 5;
        const uint32_t sb = sbase + (uint32_t)st * STAGEB;
        #pragma unroll
        for (int i = 0; i < 8; ++i) {
            int idx  = i * 256 + tid;           // 0..2047
            int tile = idx >> 9;                // 0..3
            int row  = (idx >> 2) & 127;
            int u    = idx & 3;                 // 16B unit in row
            const __nv_bfloat16* src;
            if (tile < 2)
                src = g_Xs + (size_t)tile * XPLANE + (size_t)(jBase + row) * NIN + d0 + u * 8;
            else
                src = g_As + (size_t)(tile - 2) * APLANE + (size_t)(kBase + row) * NIN + d0 + u * 8;
            cp_async16(sb + (uint32_t)tile * TILEB + (uint32_t)(row * ROWB + u * 16), src);
        }
        asm volatile("cp.async.commit_group;" ::: "memory");
    };

    issue_loads(0, 0);

    for (int ch = 0; ch < NCHUNK; ++ch) {
        const int cur = ch & 1;
        if (ch + 1 < NCHUNK) {
            issue_loads(ch + 1, cur ^ 1);
            asm volatile("cp.async.wait_group 1;" ::: "memory");
        } else {
            asm volatile("cp.async.wait_group 0;" ::: "memory");
        }
        __syncthreads();

        const uint32_t stage = sbase + (uint32_t)cur * STAGEB;
        #pragma unroll
        for (int p = 0; p < 3; ++p) {           // (x0,a0) (x0,a1) (x1,a0)
            const int xp = (p == 2) ? 1 : 0;
            const int ap = (p == 1) ? 1 : 0;
            const uint32_t xt = stage + (uint32_t)xp * TILEB;
            const uint32_t at = stage + (uint32_t)(2 + ap) * TILEB;
            #pragma unroll
            for (int k16 = 0; k16 < 2; ++k16) {
                const int colb = k16 * 32 + laneColB;
                uint32_t af[4][4], bf[2][4];
                #pragma unroll
                for (int mi = 0; mi < 4; ++mi)
                    ldm_x4(af[mi], xt + (uint32_t)((wm * 64 + mi * 16 + laneRow) * ROWB + colb));
                #pragma unroll
                for (int nh = 0; nh < 2; ++nh)
                    ldm_x4(bf[nh], at + (uint32_t)((wn * 32 + nh * 16 + laneRow) * ROWB + colb));
                #pragma unroll
                for (int mi = 0; mi < 4; ++mi)
                    #pragma unroll
                    for (int ni = 0; ni < 4; ++ni)
                        mma16816(c[mi][ni], af[mi], bf[ni >> 1][ni & 1], bf[ni >> 1][(ni & 1) + 2]);
            }
        }
        __syncthreads();
    }

    // ---- epilogue: sign, hash-select, flag near-zero, reduce, atomic
    const int g  = lane >> 2;
    const int t4 = lane & 3;
    int khc[8];
    #pragma unroll
    for (int ni = 0; ni < 4; ++ni)
        #pragma unroll
        for (int e = 0; e < 2; ++e)
            khc[ni * 2 + e] = __ldg(&hc[kBase + wn * 32 + ni * 8 + t4 * 2 + e]);

    #pragma unroll
    for (int mi = 0; mi < 4; ++mi) {
        #pragma unroll
        for (int half = 0; half < 2; ++half) {
            const int j = jBase + wm * 64 + mi * 16 + half * 8 + g;
            const float bias = __ldg(&b[j]);
            int local = 0;
            #pragma unroll
            for (int ni = 0; ni < 4; ++ni) {
                #pragma unroll
                for (int e = 0; e < 2; ++e) {
                    const float v = c[mi][ni][half * 2 + e] + bias;
                    const int bit = v > 0.f;
                    if (bit) local += khc[ni * 2 + e];
                    if (fabsf(v) < TH) {
                        const int k = kBase + wn * 32 + ni * 8 + t4 * 2 + e;
                        int slot = atomicAdd(&g_nflag, 1);
                        if (slot < FCAP) g_flags[slot] = (j << 13) | (k << 1) | bit;
                    }
                }
            }
            local += __shfl_xor_sync(0xFFFFFFFFu, local, 1);
            local += __shfl_xor_sync(0xFFFFFFFFu, local, 2);
            if (t4 == 0) atomicAdd(&g_acc[j], local);
        }
    }
}

// ---------------------------------------------------------------- kernel 3: exact fp32 fixup
__global__ __launch_bounds__(256) void fixup_kernel(const float* __restrict__ A,
                                                    const float* __restrict__ b,
                                                    const int*   __restrict__ hc)
{
    const int lane = threadIdx.x & 31;
    const int w    = (blockIdx.x * blockDim.x + threadIdx.x) >> 5;
    const int nw   = (gridDim.x * blockDim.x) >> 5;
    int n = g_nflag;
    if (n > FCAP) n = FCAP;

    for (int e = w; e < n; e += nw) {
        const int f  = g_flags[e];
        const int j  = f >> 13;
        const int k  = (f >> 1) & 0xFFF;
        const int ob = f & 1;
        const float4* xr = (const float4*)(g_Xf + (size_t)j * NIN);
        const float4* ar = (const float4*)(A    + (size_t)k * NIN);
        float s = 0.f;
        #pragma unroll 4
        for (int d = lane; d < NIN / 4; d += 32) {
            float4 xv = xr[d], av = ar[d];
            s = fmaf(xv.x, av.x, s);
            s = fmaf(xv.y, av.y, s);
            s = fmaf(xv.z, av.z, s);
            s = fmaf(xv.w, av.w, s);
        }
        #pragma unroll
        for (int o = 16; o; o >>= 1) s += __shfl_xor_sync(0xFFFFFFFFu, s, o);
        if (lane == 0) {
            const int nb = (s + b[j]) > 0.f;
            if (nb != ob) atomicAdd(&g_acc[j], nb ? hc[k] : -hc[k]);
        }
    }
}

// ---------------------------------------------------------------- kernel 4: mod, gather, map
__global__ __launch_bounds__(256) void finalize_kernel(const int* __restrict__ table,
                                                       float* __restrict__ out)
{
    int j = blockIdx.x * 256 + threadIdx.x;
    if (j < B_N) {
        int idx = g_acc[j] & TABLE_MASK;
        float cp1 = (float)table[idx] + 1.0f;
        out[j] = 1.0f / (cp1 * cp1);
    }
}

// ---------------------------------------------------------------- launch
extern "C" void kernel_launch(void* const* d_in, const int* in_sizes, int n_in,
                              void* d_out, int out_size)
{
    const float* states  = (const float*)d_in[0];
    const float* actions = (const float*)d_in[1];
    const float* A       = (const float*)d_in[2];
    const float* b       = (const float*)d_in[3];
    const int*   table   = (const int*)  d_in[4];
    const int*   hc      = (const int*)  d_in[5];
    float* out = (float*)d_out;

    static int attr_set = 0;            // host-side only; device work identical every call
    if (!attr_set) {
        cudaFuncSetAttribute(gemm_tc, cudaFuncAttributeMaxDynamicSharedMemorySize, DYNSMEM);
        attr_set = 1;
    }

    split_kernel<<<(XPLANE + APLANE + 255) / 256, 256>>>(states, actions, A);

    dim3 grid(K_N / BN, B_N / BM);      // (32, 16) = 512 CTAs
    gemm_tc<<<grid, 256, DYNSMEM>>>(b, hc);

    fixup_kernel<<<64, 256>>>(A, b, hc);

    finalize_kernel<<<(B_N + 255) / 256, 256>>>(table, out);
}

// round 8
// speedup vs baseline: 2.5407x; 1.4443x over previous
#include <cuda_runtime.h>
#include <cuda_fp16.h>
#include <cstdint>

// ---------------------------------------------------------------- dims
#define B_N   2048
#define D_IN  2047
#define NIN   2048
#define K_N   4096
#define TABLE_MASK ((1 << 22) - 1)

#define BM 128
#define BN 128
#define BK 32
#define NCHUNK (NIN / BK)          // 64
#define XPLANE (B_N * NIN)         // 4194304
#define APLANE (K_N * NIN)         // 8388608

#define ROWB  80                   // padded smem row: 32 fp16 = 64B data + 16B pad
#define TILEB (128 * ROWB)         // 10240 B per tile
#define STAGEB (2 * TILEB)         // x, a tiles = 20480 B
#define NSTAGE 3
#define DYNSMEM (NSTAGE * STAGEB)  // 61440 B

#define TH   0.15f
#define FCAP 131072

// ---------------------------------------------------------------- scratch
__device__ __align__(16) float  g_Xf[XPLANE];    // fp32 packed X (exact fixup)
__device__ __align__(16) __half g_Xh[XPLANE];    // fp16 X
__device__ __align__(16) __half g_Ah[APLANE];    // fp16 A
__device__ int g_acc[B_N];
__device__ int g_nflag;
__device__ int g_flags[FCAP];

// ---------------------------------------------------------------- helpers
__device__ __forceinline__ uint32_t smem_u32(const void* p) {
    uint32_t a;
    asm("{ .reg .u64 t; cvta.to.shared.u64 t, %1; cvt.u32.u64 %0, t; }" : "=r"(a) : "l"(p));
    return a;
}
__device__ __forceinline__ void cp_async16(uint32_t dst, const void* src) {
    asm volatile("cp.async.cg.shared.global [%0], [%1], 16;" :: "r"(dst), "l"(src) : "memory");
}
__device__ __forceinline__ void ldm_x4(uint32_t* r, uint32_t addr) {
    asm volatile("ldmatrix.sync.aligned.m8n8.x4.shared.b16 {%0,%1,%2,%3}, [%4];"
                 : "=r"(r[0]), "=r"(r[1]), "=r"(r[2]), "=r"(r[3]) : "r"(addr));
}
__device__ __forceinline__ void mma16816(float* d, const uint32_t* a, uint32_t b0, uint32_t b1) {
    asm volatile("mma.sync.aligned.m16n8k16.row.col.f32.f16.f16.f32 "
                 "{%0,%1,%2,%3},{%4,%5,%6,%7},{%8,%9},{%0,%1,%2,%3};"
                 : "+f"(d[0]), "+f"(d[1]), "+f"(d[2]), "+f"(d[3])
                 : "r"(a[0]), "r"(a[1]), "r"(a[2]), "r"(a[3]), "r"(b0), "r"(b1));
}

// ---------------------------------------------------------------- kernel 1: pack + fp16 convert
__global__ __launch_bounds__(256) void split_kernel(const float* __restrict__ states,
                                                    const float* __restrict__ actions,
                                                    const float* __restrict__ A)
{
    unsigned t = blockIdx.x * 256u + threadIdx.x;
    if (t < B_N) g_acc[t] = 0;
    if (t == 0) g_nflag = 0;

    if (t < XPLANE) {
        unsigned j = t >> 11, d = t & (NIN - 1);
        float v = (d < D_IN) ? states[j * D_IN + d] : actions[j];
        g_Xf[t] = v;
        g_Xh[t] = __float2half_rn(v);
    } else {
        unsigned e = t - XPLANE;
        if (e < APLANE) g_Ah[e] = __float2half_rn(A[e]);
    }
}

// ---------------------------------------------------------------- kernel 2: fp16 HMMA GEMM + sign + hash
// C[j,k] = Xh[j,:].Ah[k,:] (fp32 accum). sign(C + b[j]) selects hc[k].
// |C+b| < TH flagged for exact fp32 fixup (error sigma ~0.01-0.02, TH >= 8 sigma).
__global__ __launch_bounds__(256, 2) void gemm_tc(const float* __restrict__ b,
                                                  const int*   __restrict__ hc)
{
    extern __shared__ __align__(128) unsigned char dynsmem[];
    const uint32_t sbase = smem_u32(dynsmem);

    const int tid  = threadIdx.x;
    const int wid  = tid >> 5;
    const int lane = tid & 31;
    const int wm   = wid & 1;          // 2 warps over M
    const int wn   = wid >> 1;         // 4 warps over N
    const int jBase = blockIdx.y * BM;
    const int kBase = blockIdx.x * BN;

    const int laneRow  = (lane & 7) + ((lane >> 3) & 1) * 8;
    const int laneColB = ((lane >> 4) * 8) * 2;

    float c[4][4][4];
    #pragma unroll
    for (int mi = 0; mi < 4; ++mi)
        #pragma unroll
        for (int ni = 0; ni < 4; ++ni)
            #pragma unroll
            for (int e = 0; e < 4; ++e) c[mi][ni][e] = 0.f;

    // producer: chunk ch (d-range [ch*32,ch*32+32)) -> stage st. 2 tiles: X, A.
    auto issue_loads = [&](int ch, int st) {
        const int d0 = ch << 5;
        const uint32_t sb = sbase + (uint32_t)st * STAGEB;
        #pragma unroll
        for (int i = 0; i < 4; ++i) {
            int idx  = i * 256 + tid;           // 0..1023
            int tile = idx >> 9;                // 0..1
            int row  = (idx >> 2) & 127;
            int u    = idx & 3;
            const __half* src = tile ?
                (g_Ah + (size_t)(kBase + row) * NIN + d0 + u * 8) :
                (g_Xh + (size_t)(jBase + row) * NIN + d0 + u * 8);
            cp_async16(sb + (uint32_t)tile * TILEB + (uint32_t)(row * ROWB + u * 16), src);
        }
        asm volatile("cp.async.commit_group;" ::: "memory");
    };

    issue_loads(0, 0);
    issue_loads(1, 1);

    for (int ch = 0; ch < NCHUNK; ++ch) {
        if (ch + 2 < NCHUNK) {
            issue_loads(ch + 2, (ch + 2) % NSTAGE);     // stage was consumed at ch-1
            asm volatile("cp.async.wait_group 2;" ::: "memory");
        } else if (ch + 1 < NCHUNK) {
            asm volatile("cp.async.wait_group 1;" ::: "memory");
        } else {
            asm volatile("cp.async.wait_group 0;" ::: "memory");
        }
        __syncthreads();

        const uint32_t stage = sbase + (uint32_t)(ch % NSTAGE) * STAGEB;
        const uint32_t xt = stage;
        const uint32_t at = stage + TILEB;
        #pragma unroll
        for (int k16 = 0; k16 < 2; ++k16) {
            const int colb = k16 * 32 + laneColB;
            uint32_t af[4][4], bf[2][4];
            #pragma unroll
            for (int mi = 0; mi < 4; ++mi)
                ldm_x4(af[mi], xt + (uint32_t)((wm * 64 + mi * 16 + laneRow) * ROWB + colb));
            #pragma unroll
            for (int nh = 0; nh < 2; ++nh)
                ldm_x4(bf[nh], at + (uint32_t)((wn * 32 + nh * 16 + laneRow) * ROWB + colb));
            #pragma unroll
            for (int mi = 0; mi < 4; ++mi)
                #pragma unroll
                for (int ni = 0; ni < 4; ++ni)
                    mma16816(c[mi][ni], af[mi], bf[ni >> 1][ni & 1], bf[ni >> 1][(ni & 1) + 2]);
        }
        __syncthreads();
    }

    // ---- epilogue: sign, hash-select, flag near-zero, reduce, atomic
    const int g  = lane >> 2;
    const int t4 = lane & 3;
    int khc[8];
    #pragma unroll
    for (int ni = 0; ni < 4; ++ni)
        #pragma unroll
        for (int e = 0; e < 2; ++e)
            khc[ni * 2 + e] = __ldg(&hc[kBase + wn * 32 + ni * 8 + t4 * 2 + e]);

    #pragma unroll
    for (int mi = 0; mi < 4; ++mi) {
        #pragma unroll
        for (int half = 0; half < 2; ++half) {
            const int j = jBase + wm * 64 + mi * 16 + half * 8 + g;
            const float bias = __ldg(&b[j]);
            int local = 0;
            #pragma unroll
            for (int ni = 0; ni < 4; ++ni) {
                #pragma unroll
                for (int e = 0; e < 2; ++e) {
                    const float v = c[mi][ni][half * 2 + e] + bias;
                    const int bit = v > 0.f;
                    if (bit) local += khc[ni * 2 + e];
                    if (fabsf(v) < TH) {
                        const int k = kBase + wn * 32 + ni * 8 + t4 * 2 + e;
                        int slot = atomicAdd(&g_nflag, 1);
                        if (slot < FCAP) g_flags[slot] = (j << 13) | (k << 1) | bit;
                    }
                }
            }
            local += __shfl_xor_sync(0xFFFFFFFFu, local, 1);
            local += __shfl_xor_sync(0xFFFFFFFFu, local, 2);
            if (t4 == 0) atomicAdd(&g_acc[j], local);
        }
    }
}

// ---------------------------------------------------------------- kernel 3: exact fp32 fixup
__global__ __launch_bounds__(256) void fixup_kernel(const float* __restrict__ A,
                                                    const float* __restrict__ b,
                                                    const int*   __restrict__ hc)
{
    const int lane = threadIdx.x & 31;
    const int w    = (blockIdx.x * blockDim.x + threadIdx.x) >> 5;
    const int nw   = (gridDim.x * blockDim.x) >> 5;
    int n = g_nflag;
    if (n > FCAP) n = FCAP;

    for (int e = w; e < n; e += nw) {
        const int f  = g_flags[e];
        const int j  = f >> 13;
        const int k  = (f >> 1) & 0xFFF;
        const int ob = f & 1;
        const float4* xr = (const float4*)(g_Xf + (size_t)j * NIN);
        const float4* ar = (const float4*)(A    + (size_t)k * NIN);
        float s = 0.f;
        #pragma unroll 4
        for (int d = lane; d < NIN / 4; d += 32) {
            float4 xv = xr[d], av = ar[d];
            s = fmaf(xv.x, av.x, s);
            s = fmaf(xv.y, av.y, s);
            s = fmaf(xv.z, av.z, s);
            s = fmaf(xv.w, av.w, s);
        }
        #pragma unroll
        for (int o = 16; o; o >>= 1) s += __shfl_xor_sync(0xFFFFFFFFu, s, o);
        if (lane == 0) {
            const int nb = (s + b[j]) > 0.f;
            if (nb != ob) atomicAdd(&g_acc[j], nb ? hc[k] : -hc[k]);
        }
    }
}

// ---------------------------------------------------------------- kernel 4: mod, gather, map
__global__ __launch_bounds__(256) void finalize_kernel(const int* __restrict__ table,
                                                       float* __restrict__ out)
{
    int j = blockIdx.x * 256 + threadIdx.x;
    if (j < B_N) {
        int idx = g_acc[j] & TABLE_MASK;
        float cp1 = (float)table[idx] + 1.0f;
        out[j] = 1.0f / (cp1 * cp1);
    }
}

// ---------------------------------------------------------------- launch
extern "C" void kernel_launch(void* const* d_in, const int* in_sizes, int n_in,
                              void* d_out, int out_size)
{
    const float* states  = (const float*)d_in[0];
    const float* actions = (const float*)d_in[1];
    const float* A       = (const float*)d_in[2];
    const float* b       = (const float*)d_in[3];
    const int*   table   = (const int*)  d_in[4];
    const int*   hc      = (const int*)  d_in[5];
    float* out = (float*)d_out;

    static int attr_set = 0;            // host-side only; device work identical every call
    if (!attr_set) {
        cudaFuncSetAttribute(gemm_tc, cudaFuncAttributeMaxDynamicSharedMemorySize, DYNSMEM);
        attr_set = 1;
    }

    split_kernel<<<(XPLANE + APLANE + 255) / 256, 256>>>(states, actions, A);

    dim3 grid(K_N / BN, B_N / BM);      // (32, 16) = 512 CTAs
    gemm_tc<<<grid, 256, DYNSMEM>>>(b, hc);

    fixup_kernel<<<64, 256>>>(A, b, hc);

    finalize_kernel<<<(B_N + 255) / 256, 256>>>(table, out);
}

// round 10
// speedup vs baseline: 2.8870x; 1.1363x over previous
#include <cuda_runtime.h>
#include <cuda_fp16.h>
#include <cstdint>

// ---------------------------------------------------------------- dims
#define B_N   2048
#define D_IN  2047
#define NIN   2048
#define K_N   4096
#define TABLE_MASK ((1 << 22) - 1)

#define BM 128
#define BN 128
#define BK 64
#define NCHUNK (NIN / BK)          // 32
#define XPLANE (B_N * NIN)         // 4194304
#define APLANE (K_N * NIN)         // 8388608

#define ROWB  144                  // 64 fp16 = 128B data + 16B pad (16r mod 128: conflict-free)
#define TILEB (128 * ROWB)         // 18432 B per tile
#define STAGEB (2 * TILEB)         // x, a tiles = 36864 B
#define NSTAGE 3
#define DYNSMEM (NSTAGE * STAGEB)  // 110592 B

#define TH   0.15f
#define FCAP 131072

// ---------------------------------------------------------------- scratch
__device__ __align__(16) float  g_Xf[XPLANE];    // fp32 packed X (exact fixup; keep byte-identical)
__device__ __align__(16) __half g_Xh[XPLANE];    // fp16 X
__device__ __align__(16) __half g_Ah[APLANE];    // fp16 A
__device__ int g_acc[B_N];
__device__ int g_nflag;
__device__ int g_flags[FCAP];

// ---------------------------------------------------------------- helpers
__device__ __forceinline__ uint32_t smem_u32(const void* p) {
    uint32_t a;
    asm("{ .reg .u64 t; cvta.to.shared.u64 t, %1; cvt.u32.u64 %0, t; }" : "=r"(a) : "l"(p));
    return a;
}
__device__ __forceinline__ void cp_async16(uint32_t dst, const void* src) {
    asm volatile("cp.async.cg.shared.global [%0], [%1], 16;" :: "r"(dst), "l"(src) : "memory");
}
__device__ __forceinline__ void ldm_x4(uint32_t* r, uint32_t addr) {
    asm volatile("ldmatrix.sync.aligned.m8n8.x4.shared.b16 {%0,%1,%2,%3}, [%4];"
                 : "=r"(r[0]), "=r"(r[1]), "=r"(r[2]), "=r"(r[3]) : "r"(addr));
}
__device__ __forceinline__ void mma16816(float* d, const uint32_t* a, uint32_t b0, uint32_t b1) {
    asm volatile("mma.sync.aligned.m16n8k16.row.col.f32.f16.f16.f32 "
                 "{%0,%1,%2,%3},{%4,%5,%6,%7},{%8,%9},{%0,%1,%2,%3};"
                 : "+f"(d[0]), "+f"(d[1]), "+f"(d[2]), "+f"(d[3])
                 : "r"(a[0]), "r"(a[1]), "r"(a[2]), "r"(a[3]), "r"(b0), "r"(b1));
}

// ---------------------------------------------------------------- kernel 1: pack + fp16 convert (vectorized)
// First XPLANE/2 threads: X d-pairs (float2 fp32 store + half2 store).
// Next APLANE/8 threads: A 8-elem groups (2x float4 read, uint4 fp16 store).
#define XHALF (XPLANE / 2)         // 2097152
#define AOCT  (APLANE / 8)         // 1048576

__global__ __launch_bounds__(256) void split_kernel(const float* __restrict__ states,
                                                    const float* __restrict__ actions,
                                                    const float* __restrict__ A)
{
    unsigned t = blockIdx.x * 256u + threadIdx.x;
    if (t < B_N) g_acc[t] = 0;
    if (t == 0) g_nflag = 0;

    if (t < XHALF) {
        unsigned j  = t >> 10;            // row
        unsigned dp = t & 1023u;          // d-pair
        unsigned d  = dp << 1;
        float f0 = states[j * D_IN + d];                              // d <= 2046 always
        float f1 = (d + 1 < D_IN) ? states[j * D_IN + d + 1] : actions[j];
        *(float2*)(g_Xf + ((size_t)j << 11) + d) = make_float2(f0, f1);
        ((__half2*)g_Xh)[t] = __halves2half2(__float2half_rn(f0), __float2half_rn(f1));
    } else {
        unsigned e = t - XHALF;
        if (e < AOCT) {
            const float4* src = (const float4*)(A + ((size_t)e << 3));
            float4 v0 = src[0], v1 = src[1];
            __half2 h0 = __halves2half2(__float2half_rn(v0.x), __float2half_rn(v0.y));
            __half2 h1 = __halves2half2(__float2half_rn(v0.z), __float2half_rn(v0.w));
            __half2 h2 = __halves2half2(__float2half_rn(v1.x), __float2half_rn(v1.y));
            __half2 h3 = __halves2half2(__float2half_rn(v1.z), __float2half_rn(v1.w));
            uint4 o;
            o.x = *(uint32_t*)&h0; o.y = *(uint32_t*)&h1;
            o.z = *(uint32_t*)&h2; o.w = *(uint32_t*)&h3;
            *(uint4*)(g_Ah + ((size_t)e << 3)) = o;
        }
    }
}

// ---------------------------------------------------------------- kernel 2: fp16 HMMA GEMM + sign + hash
// Same k16 accumulation sequence as R8 (bit-identical C values / flags).
// 3-stage ring, ONE __syncthreads per chunk (issue-after-sync).
__global__ __launch_bounds__(256, 2) void gemm_tc(const float* __restrict__ b,
                                                  const int*   __restrict__ hc)
{
    extern __shared__ __align__(128) unsigned char dynsmem[];
    const uint32_t sbase = smem_u32(dynsmem);

    const int tid  = threadIdx.x;
    const int wid  = tid >> 5;
    const int lane = tid & 31;
    const int wm   = wid & 1;          // 2 warps over M
    const int wn   = wid >> 1;         // 4 warps over N
    const int jBase = blockIdx.y * BM;
    const int kBase = blockIdx.x * BN;

    const int laneRow  = (lane & 7) + ((lane >> 3) & 1) * 8;
    const int laneColB = ((lane >> 4) * 8) * 2;

    float c[4][4][4];
    #pragma unroll
    for (int mi = 0; mi < 4; ++mi)
        #pragma unroll
        for (int ni = 0; ni < 4; ++ni)
            #pragma unroll
            for (int e = 0; e < 4; ++e) c[mi][ni][e] = 0.f;

    // producer: chunk ch (d-range [ch*64,ch*64+64)) -> stage st. 2 tiles: X, A.
    // per tile: 128 rows x 8 x 16B units = 1024 units; 2048 total / 256 thr = 8 each.
    auto issue_loads = [&](int ch, int st) {
        const int d0 = ch << 6;
        const uint32_t sb = sbase + (uint32_t)st * STAGEB;
        #pragma unroll
        for (int i = 0; i < 8; ++i) {
            int idx  = i * 256 + tid;          // 0..2047
            int tile = idx >> 10;              // 0..1
            int row  = (idx >> 3) & 127;
            int u    = idx & 7;                // 16B unit in 128B row
            const __half* src = tile ?
                (g_Ah + (size_t)(kBase + row) * NIN + d0 + u * 8) :
                (g_Xh + (size_t)(jBase + row) * NIN + d0 + u * 8);
            cp_async16(sb + (uint32_t)tile * TILEB + (uint32_t)(row * ROWB + u * 16), src);
        }
        asm volatile("cp.async.commit_group;" ::: "memory");
    };

    issue_loads(0, 0);
    issue_loads(1, 1);

    for (int ch = 0; ch < NCHUNK; ++ch) {
        if (ch + 1 < NCHUNK) {
            asm volatile("cp.async.wait_group 1;" ::: "memory");   // chunk ch landed
        } else {
            asm volatile("cp.async.wait_group 0;" ::: "memory");
        }
        __syncthreads();                      // all warps done reading stage (ch-1)%3
        if (ch + 2 < NCHUNK)
            issue_loads(ch + 2, (ch + 2) % NSTAGE);   // = stage (ch-1)%3, safe post-sync

        const uint32_t stage = sbase + (uint32_t)(ch % NSTAGE) * STAGEB;
        const uint32_t xt = stage;
        const uint32_t at = stage + TILEB;
        #pragma unroll
        for (int k16 = 0; k16 < 4; ++k16) {   // BK=64 -> 4 k16 slices, same global order as R8
            const int colb = k16 * 32 + laneColB;
            uint32_t af[4][4], bf[2][4];
            #pragma unroll
            for (int mi = 0; mi < 4; ++mi)
                ldm_x4(af[mi], xt + (uint32_t)((wm * 64 + mi * 16 + laneRow) * ROWB + colb));
            #pragma unroll
            for (int nh = 0; nh < 2; ++nh)
                ldm_x4(bf[nh], at + (uint32_t)((wn * 32 + nh * 16 + laneRow) * ROWB + colb));
            #pragma unroll
            for (int mi = 0; mi < 4; ++mi)
                #pragma unroll
                for (int ni = 0; ni < 4; ++ni)
                    mma16816(c[mi][ni], af[mi], bf[ni >> 1][ni & 1], bf[ni >> 1][(ni & 1) + 2]);
        }
    }

    // ---- epilogue: sign, hash-select, flag near-zero, reduce, atomic (unchanged)
    const int g  = lane >> 2;
    const int t4 = lane & 3;
    int khc[8];
    #pragma unroll
    for (int ni = 0; ni < 4; ++ni)
        #pragma unroll
        for (int e = 0; e < 2; ++e)
            khc[ni * 2 + e] = __ldg(&hc[kBase + wn * 32 + ni * 8 + t4 * 2 + e]);

    #pragma unroll
    for (int mi = 0; mi < 4; ++mi) {
        #pragma unroll
        for (int half = 0; half < 2; ++half) {
            const int j = jBase + wm * 64 + mi * 16 + half * 8 + g;
            const float bias = __ldg(&b[j]);
            int local = 0;
            #pragma unroll
            for (int ni = 0; ni < 4; ++ni) {
                #pragma unroll
                for (int e = 0; e < 2; ++e) {
                    const float v = c[mi][ni][half * 2 + e] + bias;
                    const int bit = v > 0.f;
                    if (bit) local += khc[ni * 2 + e];
                    if (fabsf(v) < TH) {
                        const int k = kBase + wn * 32 + ni * 8 + t4 * 2 + e;
                        int slot = atomicAdd(&g_nflag, 1);
                        if (slot < FCAP) g_flags[slot] = (j << 13) | (k << 1) | bit;
                    }
                }
            }
            local += __shfl_xor_sync(0xFFFFFFFFu, local, 1);
            local += __shfl_xor_sync(0xFFFFFFFFu, local, 2);
            if (t4 == 0) atomicAdd(&g_acc[j], local);
        }
    }
}

// ---------------------------------------------------------------- kernel 3: exact fp32 fixup (byte-identical to R8)
__global__ __launch_bounds__(256) void fixup_kernel(const float* __restrict__ A,
                                                    const float* __restrict__ b,
                                                    const int*   __restrict__ hc)
{
    const int lane = threadIdx.x & 31;
    const int w    = (blockIdx.x * blockDim.x + threadIdx.x) >> 5;
    const int nw   = (gridDim.x * blockDim.x) >> 5;
    int n = g_nflag;
    if (n > FCAP) n = FCAP;

    for (int e = w; e < n; e += nw) {
        const int f  = g_flags[e];
        const int j  = f >> 13;
        const int k  = (f >> 1) & 0xFFF;
        const int ob = f & 1;
        const float4* xr = (const float4*)(g_Xf + (size_t)j * NIN);
        const float4* ar = (const float4*)(A    + (size_t)k * NIN);
        float s = 0.f;
        #pragma unroll 4
        for (int d = lane; d < NIN / 4; d += 32) {
            float4 xv = xr[d], av = ar[d];
            s = fmaf(xv.x, av.x, s);
            s = fmaf(xv.y, av.y, s);
            s = fmaf(xv.z, av.z, s);
            s = fmaf(xv.w, av.w, s);
        }
        #pragma unroll
        for (int o = 16; o; o >>= 1) s += __shfl_xor_sync(0xFFFFFFFFu, s, o);
        if (lane == 0) {
            const int nb = (s + b[j]) > 0.f;
            if (nb != ob) atomicAdd(&g_acc[j], nb ? hc[k] : -hc[k]);
        }
    }
}

// ---------------------------------------------------------------- kernel 4: mod, gather, map
__global__ __launch_bounds__(256) void finalize_kernel(const int* __restrict__ table,
                                                       float* __restrict__ out)
{
    int j = blockIdx.x * 256 + threadIdx.x;
    if (j < B_N) {
        int idx = g_acc[j] & TABLE_MASK;
        float cp1 = (float)table[idx] + 1.0f;
        out[j] = 1.0f / (cp1 * cp1);
    }
}

// ---------------------------------------------------------------- launch
extern "C" void kernel_launch(void* const* d_in, const int* in_sizes, int n_in,
                              void* d_out, int out_size)
{
    const float* states  = (const float*)d_in[0];
    const float* actions = (const float*)d_in[1];
    const float* A       = (const float*)d_in[2];
    const float* b       = (const float*)d_in[3];
    const int*   table   = (const int*)  d_in[4];
    const int*   hc      = (const int*)  d_in[5];
    float* out = (float*)d_out;

    static int attr_set = 0;            // host-side only; device work identical every call
    if (!attr_set) {
        cudaFuncSetAttribute(gemm_tc, cudaFuncAttributeMaxDynamicSharedMemorySize, DYNSMEM);
        attr_set = 1;
    }

    split_kernel<<<(XHALF + AOCT + 255) / 256, 256>>>(states, actions, A);

    dim3 grid(K_N / BN, B_N / BM);      // (32, 16) = 512 CTAs
    gemm_tc<<<grid, 256, DYNSMEM>>>(b, hc);

    fixup_kernel<<<64, 256>>>(A, b, hc);

    finalize_kernel<<<(B_N + 255) / 256, 256>>>(table, out);
}

// round 12
// speedup vs baseline: 4.5896x; 1.5898x over previous
#include <cuda_runtime.h>
#include <cuda_fp16.h>
#include <cstdint>

// ---------------------------------------------------------------- dims
#define B_N   2048
#define D_IN  2047
#define NIN   2048
#define K_N   4096
#define TABLE_MASK ((1 << 22) - 1)

#define BM 128
#define BN 128
#define BK 64
#define NCHUNK (NIN / BK)          // 32
#define XPLANE (B_N * NIN)         // 4194304
#define APLANE (K_N * NIN)         // 8388608

#define TILE_BYTES 16384           // 128 rows x 128 B (no pad; XOR swizzle instead)
#define STAGEB (2 * TILE_BYTES)    // X + A = 32768 B
#define NSTAGE 3
#define DYNSMEM (NSTAGE * STAGEB)  // 98304 B

#define TH   0.15f
#define FCAP 131072

// ---------------------------------------------------------------- scratch
// Pre-tiled, pre-swizzled fp16 operands (contiguous 16 KB per (tile, chunk)):
//   byte(row, colh) = row*128 + (((colh>>3) ^ (row&7))<<4) + ((colh&7)<<1)
__device__ __align__(16)  float   g_Xf[XPLANE];                 // fp32 X (exact fixup)
__device__ __align__(128) uint8_t g_Xt[16u * 32u * TILE_BYTES]; // 8 MB  [jt][ch][tile]
__device__ __align__(128) uint8_t g_At[32u * 32u * TILE_BYTES]; // 16 MB [kt][ch][tile]
__device__ int g_acc[B_N];
__device__ int g_nflag;
__device__ int g_flags[FCAP];

// ---------------------------------------------------------------- helpers
__device__ __forceinline__ uint32_t smem_u32(const void* p) {
    uint32_t a;
    asm("{ .reg .u64 t; cvta.to.shared.u64 t, %1; cvt.u32.u64 %0, t; }" : "=r"(a) : "l"(p));
    return a;
}
__device__ __forceinline__ void mbar_init(uint32_t mb, uint32_t cnt) {
    asm volatile("mbarrier.init.shared.b64 [%0], %1;" :: "r"(mb), "r"(cnt) : "memory");
}
__device__ __forceinline__ void mbar_expect_tx(uint32_t mb, uint32_t bytes) {
    asm volatile("mbarrier.arrive.expect_tx.shared.b64 _, [%0], %1;"
                 :: "r"(mb), "r"(bytes) : "memory");
}
__device__ __forceinline__ void mbar_wait(uint32_t mb, uint32_t parity) {
    asm volatile(
        "{\n\t.reg .pred P;\n"
        "W%=:\n\tmbarrier.try_wait.parity.shared.b64 P, [%0], %1;\n"
        "\t@!P bra W%=;\n\t}"
        :: "r"(mb), "r"(parity) : "memory");
}
__device__ __forceinline__ void bulk_g2s(uint32_t dst, const void* src,
                                         uint32_t bytes, uint32_t mb) {
    asm volatile(
        "cp.async.bulk.shared::cluster.global.mbarrier::complete_tx::bytes "
        "[%0], [%1], %2, [%3];"
        :: "r"(dst), "l"(src), "r"(bytes), "r"(mb) : "memory");
}
__device__ __forceinline__ void ldm_x4(uint32_t* r, uint32_t addr) {
    asm volatile("ldmatrix.sync.aligned.m8n8.x4.shared.b16 {%0,%1,%2,%3}, [%4];"
                 : "=r"(r[0]), "=r"(r[1]), "=r"(r[2]), "=r"(r[3]) : "r"(addr));
}
__device__ __forceinline__ void mma16816(float* d, const uint32_t* a, uint32_t b0, uint32_t b1) {
    asm volatile("mma.sync.aligned.m16n8k16.row.col.f32.f16.f16.f32 "
                 "{%0,%1,%2,%3},{%4,%5,%6,%7},{%8,%9},{%0,%1,%2,%3};"
                 : "+f"(d[0]), "+f"(d[1]), "+f"(d[2]), "+f"(d[3])
                 : "r"(a[0]), "r"(a[1]), "r"(a[2]), "r"(a[3]), "r"(b0), "r"(b1));
}

// ---------------------------------------------------------------- kernel 1: pack + fp16 convert into tiled/swizzled layout
#define XHALF (XPLANE / 2)         // 2097152 (X as half2 pairs)
#define AOCT  (APLANE / 8)         // 1048576 (A as 8-elem groups = one 16B unit)

__global__ __launch_bounds__(256) void split_kernel(const float* __restrict__ states,
                                                    const float* __restrict__ actions,
                                                    const float* __restrict__ A)
{
    unsigned t = blockIdx.x * 256u + threadIdx.x;
    if (t < B_N) g_acc[t] = 0;
    if (t == 0) g_nflag = 0;

    if (t < XHALF) {
        unsigned j  = t >> 10;
        unsigned d  = (t & 1023u) << 1;
        float f0 = states[j * D_IN + d];                               // d <= 2046
        float f1 = (d + 1 < D_IN) ? states[j * D_IN + d + 1] : actions[j];
        *(float2*)(g_Xf + ((size_t)j << 11) + d) = make_float2(f0, f1);
        __half2 h = __halves2half2(__float2half_rn(f0), __float2half_rn(f1));
        unsigned jt = j >> 7, row = j & 127u;
        unsigned ch = d >> 6, colh = d & 63u;                          // colh even
        unsigned off = ((jt * 32u + ch) << 14)
                     + row * 128u
                     + (((colh >> 3) ^ (row & 7u)) << 4)
                     + ((colh & 7u) << 1);
        *(uint32_t*)(g_Xt + off) = *(uint32_t*)&h;
    } else {
        unsigned e = t - XHALF;
        if (e < AOCT) {
            unsigned k   = e >> 8;
            unsigned d8  = (e & 255u) << 3;                            // multiple of 8
            const float4* src = (const float4*)(A + ((size_t)k << 11) + d8);
            float4 v0 = src[0], v1 = src[1];
            __half2 h0 = __halves2half2(__float2half_rn(v0.x), __float2half_rn(v0.y));
            __half2 h1 = __halves2half2(__float2half_rn(v0.z), __float2half_rn(v0.w));
            __half2 h2 = __halves2half2(__float2half_rn(v1.x), __float2half_rn(v1.y));
            __half2 h3 = __halves2half2(__float2half_rn(v1.z), __float2half_rn(v1.w));
            uint4 o;
            o.x = *(uint32_t*)&h0; o.y = *(uint32_t*)&h1;
            o.z = *(uint32_t*)&h2; o.w = *(uint32_t*)&h3;
            unsigned kt = k >> 7, row = k & 127u;
            unsigned ch = d8 >> 6, u = (d8 >> 3) & 7u;
            unsigned off = ((kt * 32u + ch) << 14)
                         + row * 128u
                         + ((u ^ (row & 7u)) << 4);
            *(uint4*)(g_At + off) = o;
        }
    }
}

// ---------------------------------------------------------------- kernel 2: fp16 HMMA GEMM + sign + hash
// Tile fill via cp.async.bulk (2 ops/chunk) + mbarrier ring -> LSU issue cost gone.
// Same k16 accumulation order as R8/R10 (bit-identical C / flags).
__global__ __launch_bounds__(256, 2) void gemm_tc(const float* __restrict__ b,
                                                  const int*   __restrict__ hc)
{
    extern __shared__ __align__(128) unsigned char dynsmem[];
    __shared__ __align__(8) uint64_t s_mbar[NSTAGE];

    const uint32_t sbase = smem_u32(dynsmem);
    const uint32_t mb0   = smem_u32(&s_mbar[0]);

    const int tid  = threadIdx.x;
    const int wid  = tid >> 5;
    const int lane = tid & 31;
    const int wm   = wid & 1;          // 2 warps over M
    const int wn   = wid >> 1;         // 4 warps over N
    const int jt   = blockIdx.y;       // jBase = jt*128
    const int kt   = blockIdx.x;       // kBase = kt*128
    const int jBase = jt * BM;
    const int kBase = kt * BN;

    const int laneRow = (lane & 7) + ((lane >> 3) & 1) * 8;
    const int hi      = lane >> 4;     // 0/1: 16B-unit select within k16 slice

    float c[4][4][4];
    #pragma unroll
    for (int mi = 0; mi < 4; ++mi)
        #pragma unroll
        for (int ni = 0; ni < 4; ++ni)
            #pragma unroll
            for (int e = 0; e < 4; ++e) c[mi][ni][e] = 0.f;

    if (tid == 0) {
        #pragma unroll
        for (int s = 0; s < NSTAGE; ++s) mbar_init(mb0 + 8u * s, 1);
    }
    __syncthreads();
    if (tid == 0) asm volatile("fence.proxy.async.shared::cta;" ::: "memory");

    auto issue = [&](int ch, int s) {   // tid 0 only
        const uint32_t mb = mb0 + 8u * (uint32_t)s;
        const uint32_t dx = sbase + (uint32_t)s * STAGEB;
        mbar_expect_tx(mb, STAGEB);
        bulk_g2s(dx,              g_Xt + ((size_t)(jt * 32 + ch) << 14), TILE_BYTES, mb);
        bulk_g2s(dx + TILE_BYTES, g_At + ((size_t)(kt * 32 + ch) << 14), TILE_BYTES, mb);
    };

    if (tid == 0) { issue(0, 0); issue(1, 1); }

    for (int ch = 0; ch < NCHUNK; ++ch) {
        const int st = ch % NSTAGE;
        mbar_wait(mb0 + 8u * (uint32_t)st, (uint32_t)((ch / NSTAGE) & 1));
        __syncthreads();                          // all warps done with stage (ch-1)%3
        if (ch + 2 < NCHUNK && tid == 0)
            issue(ch + 2, (ch + 2) % NSTAGE);     // = stage (ch-1)%3, safe post-sync

        const uint32_t xt = sbase + (uint32_t)st * STAGEB;
        const uint32_t at = xt + TILE_BYTES;
        #pragma unroll
        for (int k16 = 0; k16 < 4; ++k16) {       // BK=64 -> 4 k16 slices, global order as R10
            const int u = k16 * 2 + hi;
            uint32_t af[4][4], bf[2][4];
            #pragma unroll
            for (int mi = 0; mi < 4; ++mi) {
                const int r = wm * 64 + mi * 16 + laneRow;
                ldm_x4(af[mi], xt + (uint32_t)(r * 128 + ((u ^ (r & 7)) << 4)));
            }
            #pragma unroll
            for (int nh = 0; nh < 2; ++nh) {
                const int r = wn * 32 + nh * 16 + laneRow;
                ldm_x4(bf[nh], at + (uint32_t)(r * 128 + ((u ^ (r & 7)) << 4)));
            }
            #pragma unroll
            for (int mi = 0; mi < 4; ++mi)
                #pragma unroll
                for (int ni = 0; ni < 4; ++ni)
                    mma16816(c[mi][ni], af[mi], bf[ni >> 1][ni & 1], bf[ni >> 1][(ni & 1) + 2]);
        }
    }

    // ---- epilogue: sign, hash-select, flag near-zero, reduce, atomic (unchanged)
    const int g  = lane >> 2;
    const int t4 = lane & 3;
    int khc[8];
    #pragma unroll
    for (int ni = 0; ni < 4; ++ni)
        #pragma unroll
        for (int e = 0; e < 2; ++e)
            khc[ni * 2 + e] = __ldg(&hc[kBase + wn * 32 + ni * 8 + t4 * 2 + e]);

    #pragma unroll
    for (int mi = 0; mi < 4; ++mi) {
        #pragma unroll
        for (int half = 0; half < 2; ++half) {
            const int j = jBase + wm * 64 + mi * 16 + half * 8 + g;
            const float bias = __ldg(&b[j]);
            int local = 0;
            #pragma unroll
            for (int ni = 0; ni < 4; ++ni) {
                #pragma unroll
                for (int e = 0; e < 2; ++e) {
                    const float v = c[mi][ni][half * 2 + e] + bias;
                    const int bit = v > 0.f;
                    if (bit) local += khc[ni * 2 + e];
                    if (fabsf(v) < TH) {
                        const int k = kBase + wn * 32 + ni * 8 + t4 * 2 + e;
                        int slot = atomicAdd(&g_nflag, 1);
                        if (slot < FCAP) g_flags[slot] = (j << 13) | (k << 1) | bit;
                    }
                }
            }
            local += __shfl_xor_sync(0xFFFFFFFFu, local, 1);
            local += __shfl_xor_sync(0xFFFFFFFFu, local, 2);
            if (t4 == 0) atomicAdd(&g_acc[j], local);
        }
    }
}

// ---------------------------------------------------------------- kernel 3: exact fp32 fixup (unchanged math)
__global__ __launch_bounds__(256) void fixup_kernel(const float* __restrict__ A,
                                                    const float* __restrict__ b,
                                                    const int*   __restrict__ hc)
{
    const int lane = threadIdx.x & 31;
    const int w    = (blockIdx.x * blockDim.x + threadIdx.x) >> 5;
    const int nw   = (gridDim.x * blockDim.x) >> 5;
    int n = g_nflag;
    if (n > FCAP) n = FCAP;

    for (int e = w; e < n; e += nw) {
        const int f  = g_flags[e];
        const int j  = f >> 13;
        const int k  = (f >> 1) & 0xFFF;
        const int ob = f & 1;
        const float4* xr = (const float4*)(g_Xf + (size_t)j * NIN);
        const float4* ar = (const float4*)(A    + (size_t)k * NIN);
        float s = 0.f;
        #pragma unroll 4
        for (int d = lane; d < NIN / 4; d += 32) {
            float4 xv = xr[d], av = ar[d];
            s = fmaf(xv.x, av.x, s);
            s = fmaf(xv.y, av.y, s);
            s = fmaf(xv.z, av.z, s);
            s = fmaf(xv.w, av.w, s);
        }
        #pragma unroll
        for (int o = 16; o; o >>= 1) s += __shfl_xor_sync(0xFFFFFFFFu, s, o);
        if (lane == 0) {
            const int nb = (s + b[j]) > 0.f;
            if (nb != ob) atomicAdd(&g_acc[j], nb ? hc[k] : -hc[k]);
        }
    }
}

// ---------------------------------------------------------------- kernel 4: mod, gather, map
__global__ __launch_bounds__(256) void finalize_kernel(const int* __restrict__ table,
                                                       float* __restrict__ out)
{
    int j = blockIdx.x * 256 + threadIdx.x;
    if (j < B_N) {
        int idx = g_acc[j] & TABLE_MASK;
        float cp1 = (float)table[idx] + 1.0f;
        out[j] = 1.0f / (cp1 * cp1);
    }
}

// ---------------------------------------------------------------- launch
extern "C" void kernel_launch(void* const* d_in, const int* in_sizes, int n_in,
                              void* d_out, int out_size)
{
    const float* states  = (const float*)d_in[0];
    const float* actions = (const float*)d_in[1];
    const float* A       = (const float*)d_in[2];
    const float* b       = (const float*)d_in[3];
    const int*   table   = (const int*)  d_in[4];
    const int*   hc      = (const int*)  d_in[5];
    float* out = (float*)d_out;

    static int attr_set = 0;            // host-side only; device work identical every call
    if (!attr_set) {
        cudaFuncSetAttribute(gemm_tc, cudaFuncAttributeMaxDynamicSharedMemorySize, DYNSMEM);
        attr_set = 1;
    }

    split_kernel<<<(XHALF + AOCT + 255) / 256, 256>>>(states, actions, A);

    dim3 grid(K_N / BN, B_N / BM);      // (32, 16) = 512 CTAs
    gemm_tc<<<grid, 256, DYNSMEM>>>(b, hc);

    fixup_kernel<<<148, 256>>>(A, b, hc);

    finalize_kernel<<<(B_N + 255) / 256, 256>>>(table, out);
}